// round 4
// baseline (speedup 1.0000x reference)
#include <cuda_runtime.h>

// SSIM loss, separable Gaussian 11x11 on fields {s,d,s^2,d^2}, s=x+y, d=x-y.
// In-block producer/consumer pipeline: while 128 threads do the vertical conv
// (ring reads, 8 rows/thread), the other 128 stage the next chunk's global
// loads. Ring-slot bases are compile-time (template), packed f32x2 math.

namespace {
constexpr int WI = 512, HI = 512;
constexpr int SW = 64;              // strip width
constexpr int CH = 16;              // rows per produce chunk
constexpr int NCH = 4;              // chunks per block (64 output rows)
constexpr int STG2 = 84;            // SD staging row stride (u64 units, 80 used)
constexpr int RW4 = 64;             // ring row stride in float4
constexpr float C1c = 1e-4f;
constexpr float C2c = 9e-4f;
constexpr double NPIX = 25165824.0; // 32*3*512*512
constexpr unsigned NBLK = 8 * 8 * 96; // 6144 blocks
}

__device__ double g_accum;
__device__ unsigned g_done;

using u64 = unsigned long long;

__device__ __forceinline__ u64 pk(float a, float b) {
    u64 r; asm("mov.b64 %0, {%1, %2};" : "=l"(r) : "f"(a), "f"(b)); return r;
}
__device__ __forceinline__ void upk(float& a, float& b, u64 v) {
    asm("mov.b64 {%0, %1}, %2;" : "=f"(a), "=f"(b) : "l"(v));
}
__device__ __forceinline__ u64 ffma2(u64 a, u64 b, u64 c) {
    u64 d; asm("fma.rn.f32x2 %0, %1, %2, %3;" : "=l"(d) : "l"(a), "l"(b), "l"(c));
    return d;
}
__device__ __forceinline__ u64 fmul2(u64 a, u64 b) {
    u64 d; asm("mul.rn.f32x2 %0, %1, %2;" : "=l"(d) : "l"(a), "l"(b));
    return d;
}

__device__ __forceinline__ int SWZ2(int c) { return c ^ ((((c) >> 4) & 1) << 1); } // u64 units
__device__ __forceinline__ int SWZ4(int c) { return c ^ (((c) >> 3) & 7); }        // float4 units

// Vertical 11-tap conv over 18 ring rows -> 8 output rows + SSIM accumulate.
// SB = (16*v - 5 + 8*vrg) mod 32, compile-time.
template <int SB>
__device__ __forceinline__ void vert8(const float4* __restrict__ ring, int vswz,
                                      const u64* __restrict__ wp, float& acc)
{
    u64 aSD[8], aSQ[8];
    #pragma unroll
    for (int o = 0; o < 8; o++) { aSD[o] = 0ull; aSQ[o] = 0ull; }
    #pragma unroll
    for (int r = 0; r < 18; r++) {
        const int slot = (SB + r) & 31;                 // compile-time
        ulonglong2 v = *reinterpret_cast<const ulonglong2*>(ring + slot * RW4 + vswz);
        #pragma unroll
        for (int o = 0; o < 8; o++) {
            const int t = r - o;
            if (t >= 0 && t <= 10) {
                const int m = (t < 6) ? t : 10 - t;
                aSD[o] = ffma2(v.x, wp[m], aSD[o]);
                aSQ[o] = ffma2(v.y, wp[m], aSQ[o]);
            }
        }
    }
    #pragma unroll
    for (int o = 0; o < 8; o++) {
        float mus_sq, mud_sq, es, ed;
        upk(mus_sq, mud_sq, fmul2(aSD[o], aSD[o]));
        upk(es, ed, aSQ[o]);
        const float mu12  = 0.25f * (mus_sq - mud_sq);   // mu1*mu2
        const float musum = 0.5f  * (mus_sq + mud_sq);   // mu1^2+mu2^2
        const float cross = 0.25f * (es - ed);           // conv(x*y)
        const float sqsum = 0.5f  * (es + ed);           // conv(x^2)+conv(y^2)
        const float sigma12 = cross - mu12;
        const float sigsum  = sqsum - musum;
        const float num = (2.f * mu12 + C1c) * (2.f * sigma12 + C2c);
        const float den = (musum + C1c) * (sigsum + C2c);
        acc += __fdividef(num, den);
    }
}

__global__ void __launch_bounds__(256, 4) ssim_main(const float* __restrict__ img1,
                                                    const float* __restrict__ img2,
                                                    float* __restrict__ out)
{
    __shared__ u64 SD[CH][STG2];         // (s,d) packed per px
    __shared__ float4 Ring[32][RW4];     // {S,D,S2,D2} per px
    __shared__ float wsum[8];

    const float Wf[6] = {0.00102838f, 0.00759877f, 0.03600077f,
                         0.10936070f, 0.21300552f, 0.26601174f};
    u64 wp[6];
    #pragma unroll
    for (int i = 0; i < 6; i++) wp[i] = pk(Wf[i], Wf[i]);

    const int tid   = threadIdx.x;
    const int x0    = blockIdx.x * SW;
    const int segY  = blockIdx.y * (CH * NCH);
    const int plane = blockIdx.z;
    const float* p1 = img1 + (size_t)plane * (size_t)(WI * HI);
    const float* p2 = img2 + (size_t)plane * (size_t)(WI * HI);

    const int hrow = tid >> 4;           // 0..15
    const int hcg  = tid & 15;           // 0..15 (4 outputs each)
    const int vx   = tid & 63;           // vertical column
    const int vswz = SWZ4(vx);
    const float4* ringp = &Ring[0][0];

    float acc = 0.f;

    auto stageUnit = [&](int u, int yBase) {
        int r  = u / 20;
        int c4 = u - r * 20;
        int yy = yBase + r;
        int gx = x0 - 8 + c4 * 4;
        float4 a = make_float4(0.f, 0.f, 0.f, 0.f);
        float4 b = make_float4(0.f, 0.f, 0.f, 0.f);
        if ((unsigned)yy < (unsigned)HI && (unsigned)gx < (unsigned)WI) {
            a = *reinterpret_cast<const float4*>(p1 + (size_t)yy * WI + gx);
            b = *reinterpret_cast<const float4*>(p2 + (size_t)yy * WI + gx);
        }
        ulonglong2 s0, s1;
        s0.x = pk(a.x + b.x, a.x - b.x);
        s0.y = pk(a.y + b.y, a.y - b.y);
        s1.x = pk(a.z + b.z, a.z - b.z);
        s1.y = pk(a.w + b.w, a.w - b.w);
        int c = c4 * 4;
        *reinterpret_cast<ulonglong2*>(&SD[r][SWZ2(c)])     = s0;
        *reinterpret_cast<ulonglong2*>(&SD[r][SWZ2(c + 2)]) = s1;
    };

    auto horiz = [&](int p) {
        const int slot = (((p & 1) << 4) + 27 + hrow) & 31;  // (16p-5+hrow) mod 32
        u64 aSD[4] = {0ull, 0ull, 0ull, 0ull};
        u64 aSQ[4] = {0ull, 0ull, 0ull, 0ull};
        #pragma unroll
        for (int b = 1; b < 9; b++) {
            ulonglong2 v = *reinterpret_cast<const ulonglong2*>(
                &SD[hrow][SWZ2(hcg * 4 + 2 * b)]);
            #pragma unroll
            for (int e = 0; e < 2; e++) {
                const int q = 2 * b + e;
                if (q < 3 || q > 16) continue;
                const u64 sd = (e == 0) ? v.x : v.y;
                const u64 sq = fmul2(sd, sd);
                #pragma unroll
                for (int o = 0; o < 4; o++) {
                    if (q >= o + 3 && q <= o + 13) {
                        const int t = q - o - 3;
                        const int m = (t < 6) ? t : 10 - t;
                        aSD[o] = ffma2(sd, wp[m], aSD[o]);
                        aSQ[o] = ffma2(sq, wp[m], aSQ[o]);
                    }
                }
            }
        }
        #pragma unroll
        for (int o = 0; o < 4; o++) {
            ulonglong2 st; st.x = aSD[o]; st.y = aSQ[o];
            *reinterpret_cast<ulonglong2*>(&Ring[slot][SWZ4(hcg * 4 + o)]) = st;
        }
    };

    // ---- prologue: stage + horizontal for chunk 0 (all threads) ----
    {
        const int yB = segY - 5;
        for (int u = tid; u < CH * 20; u += 256) stageUnit(u, yB);
    }
    __syncthreads();
    horiz(0);
    __syncthreads();

    // ---- pipelined main loop ----
    #pragma unroll 2
    for (int k = 0; k < NCH; k++) {
        if (tid >= 128) {
            // producers: stage chunk k+1
            const int yB = segY + (k + 1) * CH - 5;
            for (int u = tid - 128; u < CH * 20; u += 128) stageUnit(u, yB);
        } else if (k >= 1) {
            // consumers: vertical + SSIM for chunk v = k-1
            if ((k & 1) == 0) {       // v odd: SB in {11, 19}
                if (tid < 64) vert8<11>(ringp, vswz, wp, acc);
                else          vert8<19>(ringp, vswz, wp, acc);
            } else {                  // v even: SB in {27, 3}
                if (tid < 64) vert8<27>(ringp, vswz, wp, acc);
                else          vert8<3>(ringp, vswz, wp, acc);
            }
        }
        __syncthreads();
        horiz(k + 1);                 // all threads
        __syncthreads();
    }

    // ---- epilogue: vertical for last chunk (v = 3, odd) ----
    if (tid < 64)       vert8<11>(ringp, vswz, wp, acc);
    else if (tid < 128) vert8<19>(ringp, vswz, wp, acc);

    // ---- block reduction -> one double atomic per block ----
    #pragma unroll
    for (int off = 16; off > 0; off >>= 1)
        acc += __shfl_down_sync(0xffffffffu, acc, off);
    if ((tid & 31) == 0) wsum[tid >> 5] = acc;
    __syncthreads();
    if (tid == 0) {
        float s = 0.f;
        #pragma unroll
        for (int i = 0; i < 8; i++) s += wsum[i];
        atomicAdd(&g_accum, (double)s);
        __threadfence();
        unsigned t = atomicAdd(&g_done, 1u);
        if (t == NBLK - 1) {
            double tot = atomicAdd(&g_accum, 0.0);   // L2-coherent read
            out[0] = (float)(1.0 - tot * (1.0 / NPIX));
            g_accum = 0.0;                            // reset for next launch
            g_done  = 0u;
        }
    }
}

extern "C" void kernel_launch(void* const* d_in, const int* in_sizes, int n_in,
                              void* d_out, int out_size) {
    (void)in_sizes; (void)n_in; (void)out_size;
    const float* img1 = (const float*)d_in[0];
    const float* img2 = (const float*)d_in[1];
    ssim_main<<<dim3(WI / SW, HI / (CH * NCH), 96), 256>>>(img1, img2, (float*)d_out);
}

// round 5
// speedup vs baseline: 1.2284x; 1.2284x over previous
#include <cuda_runtime.h>
#include <cstdint>

// SSIM loss, separable Gaussian 11x11 on fields {s,d,s^2,d^2}, s=x+y, d=x-y.
// Bulk-synchronous (all threads same role) + cp.async double-buffered raw
// staging: copy of chunk k+2/k+3 overlaps horizontal(k+1) + vertical(k).
// Packed f32x2 math, 32-slot AoS ring with compile-time slots.

namespace {
constexpr int WI = 512, HI = 512;
constexpr int SW = 64;              // strip width
constexpr int CH = 16;              // rows per chunk
constexpr int NCH = 4;              // output chunks per block (64 rows)
constexpr int RAWW = 84;            // raw row stride in floats (80 used)
constexpr float C1c = 1e-4f;
constexpr float C2c = 9e-4f;
constexpr double NPIX = 25165824.0; // 32*3*512*512
constexpr unsigned NBLK = 8 * 8 * 96;
}

__device__ double g_accum;
__device__ unsigned g_done;

using u64 = unsigned long long;

__device__ __forceinline__ u64 pk(float a, float b) {
    u64 r; asm("mov.b64 %0, {%1, %2};" : "=l"(r) : "f"(a), "f"(b)); return r;
}
__device__ __forceinline__ void upk(float& a, float& b, u64 v) {
    asm("mov.b64 {%0, %1}, %2;" : "=f"(a), "=f"(b) : "l"(v));
}
__device__ __forceinline__ u64 ffma2(u64 a, u64 b, u64 c) {
    u64 d; asm("fma.rn.f32x2 %0, %1, %2, %3;" : "=l"(d) : "l"(a), "l"(b), "l"(c));
    return d;
}
__device__ __forceinline__ u64 fmul2(u64 a, u64 b) {
    u64 d; asm("mul.rn.f32x2 %0, %1, %2;" : "=l"(d) : "l"(a), "l"(b));
    return d;
}
__device__ __forceinline__ int SWZ4(int c) { return c ^ (((c) >> 3) & 7); } // float4 units

__device__ __forceinline__ void cpasync16(uint32_t dst, const void* src, int srcsize) {
    asm volatile("cp.async.cg.shared.global [%0], [%1], 16, %2;"
                 :: "r"(dst), "l"(src), "r"(srcsize) : "memory");
}
#define CP_COMMIT()  asm volatile("cp.async.commit_group;" ::: "memory")
#define CP_WAIT(N)   asm volatile("cp.async.wait_group %0;" :: "n"(N) : "memory")

__global__ void __launch_bounds__(256, 4) ssim_main(const float* __restrict__ img1,
                                                    const float* __restrict__ img2,
                                                    float* __restrict__ out)
{
    __shared__ float Araw[2][CH][RAWW];   // raw img1 rows (double buffer)
    __shared__ float Braw[2][CH][RAWW];   // raw img2 rows
    __shared__ float4 Ring[32][64];       // {S,D,S2,D2} per px
    __shared__ float wsum[8];

    const float Wf[6] = {0.00102838f, 0.00759877f, 0.03600077f,
                         0.10936070f, 0.21300552f, 0.26601174f};
    u64 wp[6];
    #pragma unroll
    for (int i = 0; i < 6; i++) wp[i] = pk(Wf[i], Wf[i]);

    const int tid   = threadIdx.x;
    const int x0    = blockIdx.x * SW;
    const int segY  = blockIdx.y * (CH * NCH);
    const int plane = blockIdx.z;
    const float* p1 = img1 + (size_t)plane * (size_t)(WI * HI);
    const float* p2 = img2 + (size_t)plane * (size_t)(WI * HI);

    uint32_t uA, uB;
    { uint32_t t;
      asm("{ .reg .u64 x; cvta.to.shared.u64 x, %1; cvt.u32.u64 %0, x; }"
          : "=r"(t) : "l"(&Araw[0][0][0])); uA = t;
      asm("{ .reg .u64 x; cvta.to.shared.u64 x, %1; cvt.u32.u64 %0, x; }"
          : "=r"(t) : "l"(&Braw[0][0][0])); uB = t; }

    const int hrow = tid >> 4;           // 0..15
    const int hcg  = tid & 15;           // 0..15 (4 outputs each)
    const int vx   = tid & 63;
    const int vrg  = tid >> 6;           // 0..3
    const int vswz = SWZ4(vx);
    const int vb4  = vrg * 4;

    float acc = 0.f;

    // issue async copy of chunk c (c compile-time at call sites)
    auto issueChunk = [&](int c) {
        const int buf = c & 1;
        const int yB  = segY + c * CH - 5;
        #pragma unroll
        for (int i = 0; i < 3; i++) {
            int u = tid + i * 256;
            if (u < 640) {
                int img = (u >= 320) ? 1 : 0;
                int v   = u - img * 320;
                int r   = v / 20;
                int c4  = v - r * 20;
                int yy  = yB + r;
                int gx  = x0 - 8 + c4 * 4;
                bool inb = ((unsigned)yy < (unsigned)HI) && ((unsigned)gx < (unsigned)WI);
                const float* base = img ? p2 : p1;
                const float* src  = base + (size_t)(inb ? yy : 0) * WI + (inb ? gx : 0);
                uint32_t dst = (img ? uB : uA) +
                               (uint32_t)((buf * CH * RAWW + r * RAWW + c4 * 4) * 4);
                cpasync16(dst, src, inb ? 16 : 0);
            }
        }
        CP_COMMIT();
    };

    // horizontal conv of chunk p (compile-time): raw -> ring
    auto horiz = [&](int p) {
        const int buf  = p & 1;
        const int slot = (((p & 1) << 4) + 27 + hrow) & 31;   // (16p-5+hrow) mod 32
        u64 aSD[4] = {0ull, 0ull, 0ull, 0ull};
        u64 aSQ[4] = {0ull, 0ull, 0ull, 0ull};
        #pragma unroll
        for (int b = 0; b < 5; b++) {
            float4 av = *reinterpret_cast<const float4*>(&Araw[buf][hrow][(hcg + b) * 4]);
            float4 bv = *reinterpret_cast<const float4*>(&Braw[buf][hrow][(hcg + b) * 4]);
            const float ae[4] = {av.x, av.y, av.z, av.w};
            const float be[4] = {bv.x, bv.y, bv.z, bv.w};
            #pragma unroll
            for (int e = 0; e < 4; e++) {
                const int q = 4 * b + e;          // rel staged idx
                if (q < 3 || q > 16) continue;
                const u64 sd = pk(ae[e] + be[e], ae[e] - be[e]);
                const u64 sq = fmul2(sd, sd);
                #pragma unroll
                for (int o = 0; o < 4; o++) {
                    const int t = q - 3 - o;
                    if (t >= 0 && t <= 10) {
                        const int m = (t < 6) ? t : 10 - t;
                        aSD[o] = ffma2(sd, wp[m], aSD[o]);
                        aSQ[o] = ffma2(sq, wp[m], aSQ[o]);
                    }
                }
            }
        }
        #pragma unroll
        for (int o = 0; o < 4; o++) {
            ulonglong2 st; st.x = aSD[o]; st.y = aSQ[o];
            *reinterpret_cast<ulonglong2*>(&Ring[slot][SWZ4(hcg * 4 + o)]) = st;
        }
    };

    // vertical conv + SSIM for chunk k (compile-time), 4 rows/thread
    auto vert = [&](int k) {
        u64 aSD[4] = {0ull, 0ull, 0ull, 0ull};
        u64 aSQ[4] = {0ull, 0ull, 0ull, 0ull};
        #pragma unroll
        for (int r = 0; r < 14; r++) {
            const int slot = (k * CH - 5 + r + vb4 + 32) & 31;
            ulonglong2 v = *reinterpret_cast<const ulonglong2*>(&Ring[slot][vswz]);
            #pragma unroll
            for (int o = 0; o < 4; o++) {
                const int t = r - o;
                if (t >= 0 && t <= 10) {
                    const int m = (t < 6) ? t : 10 - t;
                    aSD[o] = ffma2(v.x, wp[m], aSD[o]);
                    aSQ[o] = ffma2(v.y, wp[m], aSQ[o]);
                }
            }
        }
        #pragma unroll
        for (int o = 0; o < 4; o++) {
            float mus_sq, mud_sq, es, ed;
            upk(mus_sq, mud_sq, fmul2(aSD[o], aSD[o]));
            upk(es, ed, aSQ[o]);
            const float mu12  = 0.25f * (mus_sq - mud_sq);
            const float musum = 0.5f  * (mus_sq + mud_sq);
            const float cross = 0.25f * (es - ed);
            const float sqsum = 0.5f  * (es + ed);
            const float sigma12 = cross - mu12;
            const float sigsum  = sqsum - musum;
            const float num = (2.f * mu12 + C1c) * (2.f * sigma12 + C2c);
            const float den = (musum + C1c) * (sigsum + C2c);
            acc += __fdividef(num, den);
        }
    };

    // ---- prologue ----
    issueChunk(0);
    issueChunk(1);
    CP_WAIT(1);                 // g0 done (g1 may fly)
    __syncthreads();
    horiz(0);
    __syncthreads();
    issueChunk(2);

    // ---- pipelined main loop (fully unrolled; chunks 0..4, outputs 0..3) ----
    #pragma unroll
    for (int k = 0; k < NCH; k++) {
        if (k < 3) { CP_WAIT(1); } else { CP_WAIT(0); }   // g_{k+1} done
        __syncthreads();                                   // raw visible; ring reads done
        horiz(k + 1);
        __syncthreads();
        if (k == 0) issueChunk(3);
        if (k == 1) issueChunk(4);
        vert(k);                                           // overlaps in-flight copies
    }

    // ---- block reduction -> one double atomic per block ----
    #pragma unroll
    for (int off = 16; off > 0; off >>= 1)
        acc += __shfl_down_sync(0xffffffffu, acc, off);
    if ((tid & 31) == 0) wsum[tid >> 5] = acc;
    __syncthreads();
    if (tid == 0) {
        float s = 0.f;
        #pragma unroll
        for (int i = 0; i < 8; i++) s += wsum[i];
        atomicAdd(&g_accum, (double)s);
        __threadfence();
        unsigned t = atomicAdd(&g_done, 1u);
        if (t == NBLK - 1) {
            double tot = atomicAdd(&g_accum, 0.0);
            out[0] = (float)(1.0 - tot * (1.0 / NPIX));
            g_accum = 0.0;
            g_done  = 0u;
        }
    }
}

extern "C" void kernel_launch(void* const* d_in, const int* in_sizes, int n_in,
                              void* d_out, int out_size) {
    (void)in_sizes; (void)n_in; (void)out_size;
    const float* img1 = (const float*)d_in[0];
    const float* img2 = (const float*)d_in[1];
    ssim_main<<<dim3(WI / SW, HI / (CH * NCH), 96), 256>>>(img1, img2, (float*)d_out);
}